// round 4
// baseline (speedup 1.0000x reference)
#include <cuda_runtime.h>

// Shapes: depth_map/x_ray [8,1,512,512] fp32 -> out [8,1,128,128,128] fp32
#define NB   8
#define INHW 512
#define RHW  128   // resized H=W
#define ND   128   // depth bins

// Intermediate buffers (device globals: allocation-free scratch)
__device__ float g_xr[NB * RHW * RHW];
__device__ int   g_di[NB * RHW * RHW];

// ---------------------------------------------------------------------------
// Kernel 1: jax.image.resize(bilinear, antialias=True) 512->128 both arrays,
// plus depth->index conversion. Block = (h_out, b), 128 threads = w_out.
// Separable: vertical 8-tap reduce into smem row (512 wide), then horizontal
// 8-tap per output pixel. Raw triangle weights {1,3,5,7,7,5,3,1}/8,
// normalized by the in-range weight sum (matches jax edge renormalization).
// ---------------------------------------------------------------------------
__global__ __launch_bounds__(128) void resize_kernel(const float* __restrict__ depth,
                                                     const float* __restrict__ xray) {
    const int h   = blockIdx.x;
    const int b   = blockIdx.y;
    const int tid = threadIdx.x;

    __shared__ float tmpd[INHW];
    __shared__ float tmpx[INHW];

    const float RW[8] = {0.125f, 0.375f, 0.625f, 0.875f,
                         0.875f, 0.625f, 0.375f, 0.125f};

    float ad[4] = {0.f, 0.f, 0.f, 0.f};
    float ax[4] = {0.f, 0.f, 0.f, 0.f};
    float wsv = 0.f;

    #pragma unroll
    for (int t = 0; t < 8; ++t) {
        int j = 4 * h - 2 + t;                 // input row
        if (j < 0 || j > INHW - 1) continue;   // uniform across block
        float wv = RW[t];
        wsv += wv;
        const float* drow = depth + ((size_t)b * INHW + j) * INHW;
        const float* xrow = xray  + ((size_t)b * INHW + j) * INHW;
        #pragma unroll
        for (int k = 0; k < 4; ++k) {
            int c = tid + k * 128;
            ad[k] = fmaf(wv, drow[c], ad[k]);
            ax[k] = fmaf(wv, xrow[c], ax[k]);
        }
    }
    #pragma unroll
    for (int k = 0; k < 4; ++k) {
        tmpd[tid + k * 128] = ad[k];
        tmpx[tid + k * 128] = ax[k];
    }
    __syncthreads();

    float sd = 0.f, sx = 0.f, wsh = 0.f;
    #pragma unroll
    for (int t = 0; t < 8; ++t) {
        int c = 4 * tid - 2 + t;               // input col
        if ((unsigned)c < (unsigned)INHW) {
            float wv = RW[t];
            wsh += wv;
            sd = fmaf(wv, tmpd[c], sd);
            sx = fmaf(wv, tmpx[c], sx);
        }
    }
    float inv = 1.f / (wsv * wsh);
    float dv  = sd * inv;                      // resized depth
    float xv  = sx * inv;                      // resized x_ray

    // d_idx = clip(int((depth/100)*127), 0, 127)  (truncation; depth >= 0)
    int di = (int)((dv / 100.f) * 127.f);
    di = di < 0 ? 0 : (di > ND - 1 ? ND - 1 : di);

    int idx = (b * RHW + h) * RHW + tid;
    g_xr[idx] = xv;
    g_di[idx] = di;
}

// ---------------------------------------------------------------------------
// Kernel 2: fused gaussian depth splat + 3x3x3 avg pool (/27, include_pad).
// Block = (h, b), 128 threads = w. Each thread owns one output column of 128
// depths, accumulated in 64KB dynamic smem laid out d-major: vol[d*128 + w]
// -> thread w always hits bank w%32: zero conflicts for zeroing, the
// scatter-adds, and the final coalesced stores.
// Output column = sum over 9 spatial neighbors of a <=7-wide depth bump:
// each valid splat target dt = di+o (|o|<=2, 0<=dt<128) with weight g[o]
// spreads (via the depth pool) to output depths dt-1, dt, dt+1 (in range).
// ---------------------------------------------------------------------------
__global__ __launch_bounds__(128) void splat_pool_kernel(float* __restrict__ out) {
    extern __shared__ float vol[];             // [128 d][128 w], d-major, 64KB
    __shared__ float sx[3][130];
    __shared__ int   sdi[3][130];

    const int h = blockIdx.x;
    const int b = blockIdx.y;
    const int w = threadIdx.x;

    #pragma unroll
    for (int dh = 0; dh < 3; ++dh) {
        int hh = h + dh - 1;
        bool v = (hh >= 0) && (hh < RHW);
        int idx = (b * RHW + (v ? hh : 0)) * RHW + w;
        sx[dh][w + 1]  = v ? g_xr[idx] : 0.f;
        sdi[dh][w + 1] = v ? g_di[idx] : 0;
    }
    if (w == 0) {
        #pragma unroll
        for (int dh = 0; dh < 3; ++dh) {
            sx[dh][0]  = 0.f; sx[dh][129]  = 0.f;   // zero-pad in w
            sdi[dh][0] = 0;   sdi[dh][129] = 0;
        }
    }
    #pragma unroll
    for (int d = 0; d < ND; ++d) vol[d * 128 + w] = 0.f;
    __syncthreads();

    const float gw[5] = {0.13533528324f,   // exp(-2)
                         0.60653065971f,   // exp(-0.5)
                         1.0f,
                         0.60653065971f,
                         0.13533528324f};

    #pragma unroll
    for (int dh = 0; dh < 3; ++dh) {
        #pragma unroll
        for (int dw = 0; dw < 3; ++dw) {
            float xv = sx[dh][w + dw];
            if (xv == 0.f) continue;           // padding (or exact-zero: no-op)
            int di = sdi[dh][w + dw];

            float bump[7] = {0.f, 0.f, 0.f, 0.f, 0.f, 0.f, 0.f};
            #pragma unroll
            for (int o = 0; o < 5; ++o) {
                int dt = di + o - 2;           // splat target
                if ((unsigned)dt < (unsigned)ND) {
                    float v = gw[o];
                    bump[o]     += v;          // pooled to dt-1
                    bump[o + 1] += v;          // pooled to dt
                    bump[o + 2] += v;          // pooled to dt+1
                }
            }
            #pragma unroll
            for (int t = 0; t < 7; ++t) {
                int d = di + t - 3;
                if ((unsigned)d < (unsigned)ND)
                    vol[d * 128 + w] += xv * bump[t];
            }
        }
    }
    // Each thread only touched its own column w: no sync needed before readout.

    const float inv27 = 1.0f / 27.0f;
    float* obase = out + (size_t)b * (ND * RHW * RHW) + (size_t)h * RHW + w;
    #pragma unroll 16
    for (int d = 0; d < ND; ++d)
        obase[(size_t)d * (RHW * RHW)] = vol[d * 128 + w] * inv27;
}

// ---------------------------------------------------------------------------
extern "C" void kernel_launch(void* const* d_in, const int* in_sizes, int n_in,
                              void* d_out, int out_size) {
    const float* depth = (const float*)d_in[0];   // [8,1,512,512] fp32
    const float* xray  = (const float*)d_in[1];   // [8,1,512,512] fp32
    float* out = (float*)d_out;                   // [8,1,128,128,128] fp32

    (void)in_sizes; (void)n_in; (void)out_size;

    // 64KB dynamic smem for the column tile (above the 48KB default cap).
    cudaFuncSetAttribute(splat_pool_kernel,
                         cudaFuncAttributeMaxDynamicSharedMemorySize, 65536);

    dim3 grid(RHW, NB);
    resize_kernel<<<grid, 128>>>(depth, xray);
    splat_pool_kernel<<<grid, 128, 65536>>>(out);
}